// round 16
// baseline (speedup 1.0000x reference)
#include <cuda_runtime.h>
#include <cuda_fp16.h>
#include <cstdint>
#include <math.h>
#include <math_constants.h>

// Problem constants
#define Bq  2
#define Tq  1024
#define Dq  1024
#define Hq  16
#define FFq 4096
#define Lq  8
#define Vq  32000
#define HDq 64
#define Rq  (Bq * Tq)   // 2048 rows

// ---------------------------------------------------------------------------
// Scratch (device globals; no runtime allocation allowed)
// ---------------------------------------------------------------------------
__device__ float  g_x   [Rq * Dq];       // residual stream (fp32)
__device__ __half g_qkvh[Rq * 3 * Dq];   // q|k|v (fp16)
__device__ __half g_lnh [Rq * Dq];       // layernorm output (fp16 GEMM A)
__device__ __half g_yh  [Rq * Dq];       // attention output (fp16 GEMM A)
__device__ __half g_ffh [Rq * FFq];      // mlp hidden (fp16 GEMM A)

// k-pair-interleaved half2 weights: [K/2][N], elem = (w[2k2][n], w[2k2+1][n])
__device__ __half2 g_wqkv_h[Lq * (Dq/2) * 3 * Dq];
__device__ __half2 g_wout_h[Lq * (Dq/2) * Dq];
__device__ __half2 g_wm1_h [Lq * (Dq/2) * FFq];
__device__ __half2 g_wm2_h [Lq * (FFq/2) * Dq];
__device__ __half2 g_whd_h [(Dq/2) * Vq];

// ---------------------------------------------------------------------------
// Weight convert: fp32 [K][N] -> half2 [K/2][N], 3D grid (n4, k2, layer).
// ---------------------------------------------------------------------------
__global__ void w2h4_kernel(const float4* __restrict__ in,
                            uint4* __restrict__ out, int K, int N) {
    int n4 = blockIdx.x * blockDim.x + threadIdx.x;   // float4 column index
    int N4 = N >> 2;
    if (n4 >= N4) return;
    int k2 = blockIdx.y;
    size_t lbase = (size_t)blockIdx.z * K * N4;       // in float4 units
    float4 a = in[lbase + (size_t)(2 * k2)     * N4 + n4];
    float4 b = in[lbase + (size_t)(2 * k2 + 1) * N4 + n4];
    __half2 h0 = __floats2half2_rn(a.x, b.x);
    __half2 h1 = __floats2half2_rn(a.y, b.y);
    __half2 h2 = __floats2half2_rn(a.z, b.z);
    __half2 h3 = __floats2half2_rn(a.w, b.w);
    uint4 u;
    u.x = *(unsigned*)&h0; u.y = *(unsigned*)&h1;
    u.z = *(unsigned*)&h2; u.w = *(unsigned*)&h3;
    out[(size_t)blockIdx.z * (K / 2) * N4 + (size_t)k2 * N4 + n4] = u;
}

// ---------------------------------------------------------------------------
__global__ void embed_kernel(const int* __restrict__ idx,
                             const float* __restrict__ emb,
                             float* __restrict__ x) {
    int row = blockIdx.x;
    int t   = row % Tq;
    int tok = idx[row];
    const float* er = emb + (size_t)tok * Dq;
    const float neg_log = -logf(10000.0f) / (float)Dq;
    for (int d = threadIdx.x; d < Dq; d += blockDim.x) {
        int i2 = d & ~1;
        float freq = expf(neg_log * (float)i2);
        float ang  = (float)t * freq;
        float pe   = (d & 1) ? cosf(ang) : sinf(ang);
        x[(size_t)row * Dq + d] = er[d] + pe;
    }
}

// ---------------------------------------------------------------------------
// Warp-per-row LayerNorm (no smem, shfl-only reductions); writes fp16.
// ---------------------------------------------------------------------------
__global__ __launch_bounds__(256)
void ln_kernel(const float* __restrict__ x,
               const float* __restrict__ sc,
               const float* __restrict__ bi,
               __half* __restrict__ out) {
    int lane = threadIdx.x & 31;
    int w    = threadIdx.x >> 5;
    int row  = blockIdx.x * 8 + w;
    const float4* xr = (const float4*)(x + (size_t)row * Dq);

    float4 v[8];
    float s = 0.0f;
    #pragma unroll
    for (int i = 0; i < 8; i++) {
        v[i] = xr[lane + i * 32];
        s += v[i].x + v[i].y + v[i].z + v[i].w;
    }
    #pragma unroll
    for (int o = 16; o; o >>= 1) s += __shfl_xor_sync(0xffffffffu, s, o);
    float mean = s * (1.0f / (float)Dq);

    float q = 0.0f;
    #pragma unroll
    for (int i = 0; i < 8; i++) {
        float dx = v[i].x - mean, dy = v[i].y - mean;
        float dz = v[i].z - mean, dw = v[i].w - mean;
        q += dx * dx + dy * dy + dz * dz + dw * dw;
    }
    #pragma unroll
    for (int o = 16; o; o >>= 1) q += __shfl_xor_sync(0xffffffffu, q, o);
    float inv = rsqrtf(q * (1.0f / (float)Dq) + 1e-5f);

    #pragma unroll
    for (int i = 0; i < 8; i++) {
        int c = (lane + i * 32) * 4;
        float o0 = (v[i].x - mean) * inv * sc[c + 0] + bi[c + 0];
        float o1 = (v[i].y - mean) * inv * sc[c + 1] + bi[c + 1];
        float o2 = (v[i].z - mean) * inv * sc[c + 2] + bi[c + 2];
        float o3 = (v[i].w - mean) * inv * sc[c + 3] + bi[c + 3];
        __half2 h0 = __floats2half2_rn(o0, o1);
        __half2 h1 = __floats2half2_rn(o2, o3);
        uint2 u;
        u.x = *(unsigned*)&h0; u.y = *(unsigned*)&h1;
        *(uint2*)(out + (size_t)row * Dq + c) = u;
    }
}

// ---------------------------------------------------------------------------
// FP16 tensor-core GEMM (m16n8k16, fp32 accum), 3-stage cp.async ring, BK=32.
// (exact R10/R14 pipeline — proven)
//   EPI 0: C(fp32) = AB + bias ; EPI 1: C(fp32) += AB + bias
//   EPI 2: C(fp16) = gelu(AB + bias) ; EPI 3: C(fp16) = AB + bias
// ---------------------------------------------------------------------------
__device__ __forceinline__ void mma_f16(float c[4],
                                        unsigned a0, unsigned a1, unsigned a2, unsigned a3,
                                        unsigned b0, unsigned b1) {
    asm volatile(
        "mma.sync.aligned.m16n8k16.row.col.f32.f16.f16.f32 "
        "{%0,%1,%2,%3}, {%4,%5,%6,%7}, {%8,%9}, {%0,%1,%2,%3};"
        : "+f"(c[0]), "+f"(c[1]), "+f"(c[2]), "+f"(c[3])
        : "r"(a0), "r"(a1), "r"(a2), "r"(a3), "r"(b0), "r"(b1));
}

#define CP16(dst, src) \
    asm volatile("cp.async.cg.shared.global [%0], [%1], 16;\n" :: "r"(dst), "l"(src))

template <int EPI, int BMt>
__global__ __launch_bounds__(128)
void hgemm_kernel(const __half* __restrict__ A, const __half2* __restrict__ B2,
                  const float* __restrict__ bias, float* __restrict__ C,
                  int M, int N, int K) {
    constexpr int BK = 32;
    constexpr int ASZW = BMt * 16;
    constexpr int BSZW = 16 * 128;
    constexpr int STG  = ASZW + BSZW;
    constexpr int MI   = BMt / 32;
    extern __shared__ unsigned smw[];

    int tid  = threadIdx.x;
    int lane = tid & 31;
    int warp = tid >> 5;
    int g    = lane >> 2;
    int tig  = lane & 3;
    int wm   = warp & 1;
    int wn   = warp >> 1;
    int rm   = wm * (BMt / 2);
    int cn   = wn * 64;

    const __half*  Ab  = A + (size_t)(blockIdx.y * BMt) * K;
    const __half2* Bb2 = B2 + (size_t)blockIdx.x * 128;

    float acc[MI][8][4];
    #pragma unroll
    for (int mi = 0; mi < MI; mi++)
        #pragma unroll
        for (int ni = 0; ni < 8; ni++)
            #pragma unroll
            for (int c = 0; c < 4; c++) acc[mi][ni][c] = 0.0f;

    unsigned sBase = (unsigned)__cvta_generic_to_shared(smw);

    auto issue = [&](int kt, int p) {
        unsigned sa = sBase + (unsigned)(p * STG) * 4u;
        unsigned sb = sa + (unsigned)ASZW * 4u;
        #pragma unroll
        for (int i = 0; i < BMt / 32; i++) {
            int lin = tid + i * 128;
            int m = lin >> 2, c = lin & 3;
            const __half* src = Ab + (size_t)m * K + kt + c * 8;
            unsigned dst = sa + (unsigned)(m * 16 + ((c ^ ((m >> 1) & 3)) << 2)) * 4u;
            CP16(dst, src);
        }
        #pragma unroll
        for (int i = 0; i < 4; i++) {
            int lin = tid + i * 128;
            int k2 = lin >> 5, c4 = lin & 31;
            const __half2* src = Bb2 + (size_t)(kt / 2 + k2) * N + c4 * 4;
            unsigned dst = sb + (unsigned)(k2 * 128 + ((c4 ^ (2 * (k2 & 3))) << 2)) * 4u;
            CP16(dst, src);
        }
        asm volatile("cp.async.commit_group;\n");
    };

    int ntiles = K / BK;
    issue(0, 0);
    issue(BK, 1);

    for (int t = 0; t < ntiles; t++) {
        int p = t % 3;
        asm volatile("cp.async.wait_group 1;\n");
        __syncthreads();
        if (t + 2 < ntiles) {
            issue((t + 2) * BK, (t + 2) % 3);
        } else {
            asm volatile("cp.async.commit_group;\n");
        }

        const unsigned* Ap = smw + p * STG;
        const unsigned* Bp = Ap + ASZW;
        #pragma unroll
        for (int ksi = 0; ksi < 2; ksi++) {
            unsigned af[MI][4], bf[8][2];
            #pragma unroll
            for (int mi = 0; mi < MI; mi++) {
                int m1 = rm + mi * 16 + g;
                int m2 = m1 + 8;
                unsigned s1 = (unsigned)((m1 >> 1) & 3);
                unsigned s2 = (unsigned)((m2 >> 1) & 3);
                unsigned c0 = (unsigned)(2 * ksi);
                af[mi][0] = Ap[m1 * 16 + (((c0    ) ^ s1) << 2) + tig];
                af[mi][1] = Ap[m2 * 16 + (((c0    ) ^ s2) << 2) + tig];
                af[mi][2] = Ap[m1 * 16 + (((c0 + 1) ^ s1) << 2) + tig];
                af[mi][3] = Ap[m2 * 16 + (((c0 + 1) ^ s2) << 2) + tig];
            }
            int k2b = ksi * 8;
            #pragma unroll
            for (int ni = 0; ni < 8; ni++) {
                unsigned nb = (unsigned)(cn + ni * 8 + g);
                bf[ni][0] = Bp[(k2b + tig)     * 128 + (nb ^ (unsigned)(8 * tig))];
                bf[ni][1] = Bp[(k2b + tig + 4) * 128 + (nb ^ (unsigned)(8 * tig))];
            }
            #pragma unroll
            for (int mi = 0; mi < MI; mi++)
                #pragma unroll
                for (int ni = 0; ni < 8; ni++)
                    mma_f16(acc[mi][ni],
                            af[mi][0], af[mi][1], af[mi][2], af[mi][3],
                            bf[ni][0], bf[ni][1]);
        }
        __syncthreads();
    }

    #pragma unroll
    for (int ni = 0; ni < 8; ni++) {
        int gc = blockIdx.x * 128 + cn + ni * 8 + 2 * tig;
        float bv0 = bias ? bias[gc]     : 0.0f;
        float bv1 = bias ? bias[gc + 1] : 0.0f;
        #pragma unroll
        for (int mi = 0; mi < MI; mi++) {
            int gr1 = blockIdx.y * BMt + rm + mi * 16 + g;
            int gr2 = gr1 + 8;
            float v00 = acc[mi][ni][0] + bv0;
            float v01 = acc[mi][ni][1] + bv1;
            float v10 = acc[mi][ni][2] + bv0;
            float v11 = acc[mi][ni][3] + bv1;
            if (EPI == 0) {
                *(float2*)(C + (size_t)gr1 * N + gc) = make_float2(v00, v01);
                *(float2*)(C + (size_t)gr2 * N + gc) = make_float2(v10, v11);
            } else if (EPI == 1) {
                float2* p1 = (float2*)(C + (size_t)gr1 * N + gc);
                float2* p2 = (float2*)(C + (size_t)gr2 * N + gc);
                float2 o1 = *p1, o2 = *p2;
                *p1 = make_float2(o1.x + v00, o1.y + v01);
                *p2 = make_float2(o2.x + v10, o2.y + v11);
            } else if (EPI == 2) {
                const float is2 = 0.70710678118654752f;
                __half* Ch = (__half*)C;
                float g00 = 0.5f * v00 * (1.0f + erff(v00 * is2));
                float g01 = 0.5f * v01 * (1.0f + erff(v01 * is2));
                float g10 = 0.5f * v10 * (1.0f + erff(v10 * is2));
                float g11 = 0.5f * v11 * (1.0f + erff(v11 * is2));
                *(__half2*)(Ch + (size_t)gr1 * N + gc) = __floats2half2_rn(g00, g01);
                *(__half2*)(Ch + (size_t)gr2 * N + gc) = __floats2half2_rn(g10, g11);
            } else {
                __half* Ch = (__half*)C;
                *(__half2*)(Ch + (size_t)gr1 * N + gc) = __floats2half2_rn(v00, v01);
                *(__half2*)(Ch + (size_t)gr2 * N + gc) = __floats2half2_rn(v10, v11);
            }
        }
    }
}

// ---------------------------------------------------------------------------
// FP16 tensor-core flash attention, 128-query tile, longest-first schedule.
// One CTA per (128q, head, batch); 4 warps; warp owns 32 rows (2 m16 tiles).
// KV tiles of 64 rows. Smem words: Q[128][36] K[64][36] P[128][36] V[32][72].
// ---------------------------------------------------------------------------
#define QSTW 36
#define VSTW 72

__global__ __launch_bounds__(128)
void attn5_kernel(const __half* __restrict__ qkv, __half* __restrict__ y) {
    extern __shared__ unsigned smA[];
    unsigned* Qs = smA;                     // [128][36]
    unsigned* Ks = Qs + 128 * QSTW;         // [64][36]
    unsigned* Ps = Ks + 64 * QSTW;          // [128][36]
    unsigned* Vs = Ps + 128 * QSTW;         // [32][72]

    int qb = (gridDim.x - 1) - blockIdx.x;  // longest CTAs first
    int h = blockIdx.y, b = blockIdx.z;
    int tid = threadIdx.x;
    int lane = tid & 31, w = tid >> 5;
    int g = lane >> 2, tig = lane & 3;

    const size_t rs = 3 * Dq;               // halves
    const __half* qbase = qkv + ((size_t)(b * Tq + qb * 128)) * rs + h * HDq;
    const __half2 sc2 = __half2half2(__float2half(0.125f));  // exact pow2

    // stage Q: 128 rows x 8 chunks (16B) = 1024 / 128 = 8 iters
    #pragma unroll
    for (int i = 0; i < 8; i++) {
        int lin = tid + i * 128;
        int r = lin >> 3, c = lin & 7;
        uint4 u = *(const uint4*)(qbase + (size_t)r * rs + c * 8);
        __half2* hp = (__half2*)&u;
        hp[0] = __hmul2(hp[0], sc2); hp[1] = __hmul2(hp[1], sc2);
        hp[2] = __hmul2(hp[2], sc2); hp[3] = __hmul2(hp[3], sc2);
        *(uint4*)&Qs[r * QSTW + c * 4] = u;
    }

    float oacc[2][8][4];
    #pragma unroll
    for (int mi = 0; mi < 2; mi++)
        #pragma unroll
        for (int ni = 0; ni < 8; ni++)
            #pragma unroll
            for (int c = 0; c < 4; c++) oacc[mi][ni][c] = 0.0f;
    float mrow[4], lrow[4];
    #pragma unroll
    for (int i = 0; i < 4; i++) { mrow[i] = -CUDART_INF_F; lrow[i] = 0.0f; }

    // thread's rows: mi in {0,1}, pair p in {0,1}: rloc = w*32 + mi*16 + p*8 + g
    int rbase = w * 32 + g;

    int nkt = 2 * qb + 2;                   // 64-row kv tiles
    for (int kt = 0; kt < nkt; kt++) {
        __syncthreads();
        const __half* kbase = qkv + ((size_t)(b * Tq + kt * 64)) * rs + Dq + h * HDq;
        const __half* vbase = kbase + Dq;
        // stage K: 64 rows x 8 chunks = 512 / 128 = 4 iters
        #pragma unroll
        for (int i = 0; i < 4; i++) {
            int lin = tid + i * 128;
            int r = lin >> 3, c = lin & 7;
            uint4 u = *(const uint4*)(kbase + (size_t)r * rs + c * 8);
            *(uint4*)&Ks[r * QSTW + c * 4] = u;
        }
        // stage V: pair-gather (V[2k2][n], V[2k2+1][n]) via lows/highs
        #pragma unroll
        for (int i = 0; i < 4; i++) {
            int lin = tid + i * 128;
            int k2 = lin >> 4, q = lin & 15;
            uint2 a2 = *(const uint2*)(vbase + (size_t)(2 * k2)     * rs + q * 4);
            uint2 b2 = *(const uint2*)(vbase + (size_t)(2 * k2 + 1) * rs + q * 4);
            __half2 ax = *(__half2*)&a2.x, ay = *(__half2*)&a2.y;
            __half2 bx = *(__half2*)&b2.x, by = *(__half2*)&b2.y;
            __half2 w0 = __lows2half2(ax, bx),  w1 = __highs2half2(ax, bx);
            __half2 w2 = __lows2half2(ay, by),  w3 = __highs2half2(ay, by);
            uint4 u;
            u.x = *(unsigned*)&w0; u.y = *(unsigned*)&w1;
            u.z = *(unsigned*)&w2; u.w = *(unsigned*)&w3;
            *(uint4*)&Vs[k2 * VSTW + q * 4] = u;
        }
        __syncthreads();

        // ---- S = Q K^T : 4 k-steps of 16, 2 row-tiles ----
        float sacc[2][8][4];
        #pragma unroll
        for (int mi = 0; mi < 2; mi++)
            #pragma unroll
            for (int ni = 0; ni < 8; ni++)
                #pragma unroll
                for (int c = 0; c < 4; c++) sacc[mi][ni][c] = 0.0f;
        #pragma unroll
        for (int ksi = 0; ksi < 4; ksi++) {
            int kw = ksi * 8;
            unsigned aq[2][4];
            #pragma unroll
            for (int mi = 0; mi < 2; mi++) {
                int r0 = rbase + mi * 16;
                aq[mi][0] = Qs[(r0    ) * QSTW + kw + tig];
                aq[mi][1] = Qs[(r0 + 8) * QSTW + kw + tig];
                aq[mi][2] = Qs[(r0    ) * QSTW + kw + 4 + tig];
                aq[mi][3] = Qs[(r0 + 8) * QSTW + kw + 4 + tig];
            }
            #pragma unroll
            for (int ni = 0; ni < 8; ni++) {
                int nr = ni * 8 + g;
                unsigned b0 = Ks[nr * QSTW + kw + tig];
                unsigned b1 = Ks[nr * QSTW + kw + 4 + tig];
                #pragma unroll
                for (int mi = 0; mi < 2; mi++)
                    mma_f16(sacc[mi][ni], aq[mi][0], aq[mi][1], aq[mi][2], aq[mi][3], b0, b1);
            }
        }

        // ---- causal mask (only the last two kv tiles can cross diagonal) ----
        if (kt >= 2 * qb) {
            int coff = kt * 64 - qb * 128;   // 0 or 64
            #pragma unroll
            for (int mi = 0; mi < 2; mi++) {
                int r0 = rbase + mi * 16;
                #pragma unroll
                for (int ni = 0; ni < 8; ni++) {
                    int c0 = ni * 8 + 2 * tig + coff, c1 = c0 + 1;
                    if (c0 > r0)     sacc[mi][ni][0] = -CUDART_INF_F;
                    if (c1 > r0)     sacc[mi][ni][1] = -CUDART_INF_F;
                    if (c0 > r0 + 8) sacc[mi][ni][2] = -CUDART_INF_F;
                    if (c1 > r0 + 8) sacc[mi][ni][3] = -CUDART_INF_F;
                }
            }
        }

        // ---- online softmax per row-tile ----
        #pragma unroll
        for (int mi = 0; mi < 2; mi++) {
            float mx0 = -CUDART_INF_F, mx1 = -CUDART_INF_F;
            #pragma unroll
            for (int ni = 0; ni < 8; ni++) {
                mx0 = fmaxf(mx0, fmaxf(sacc[mi][ni][0], sacc[mi][ni][1]));
                mx1 = fmaxf(mx1, fmaxf(sacc[mi][ni][2], sacc[mi][ni][3]));
            }
            mx0 = fmaxf(mx0, __shfl_xor_sync(0xffffffffu, mx0, 1));
            mx0 = fmaxf(mx0, __shfl_xor_sync(0xffffffffu, mx0, 2));
            mx1 = fmaxf(mx1, __shfl_xor_sync(0xffffffffu, mx1, 1));
            mx1 = fmaxf(mx1, __shfl_xor_sync(0xffffffffu, mx1, 2));

            float mn0 = fmaxf(mrow[mi * 2 + 0], mx0);
            float mn1 = fmaxf(mrow[mi * 2 + 1], mx1);
            float corr0 = __expf(mrow[mi * 2 + 0] - mn0);
            float corr1 = __expf(mrow[mi * 2 + 1] - mn1);

            int r0 = rbase + mi * 16;
            float rs0 = 0.0f, rs1 = 0.0f;
            #pragma unroll
            for (int ni = 0; ni < 8; ni++) {
                __half2 h0 = __floats2half2_rn(__expf(sacc[mi][ni][0] - mn0),
                                               __expf(sacc[mi][ni][1] - mn0));
                __half2 h1 = __floats2half2_rn(__expf(sacc[mi][ni][2] - mn1),
                                               __expf(sacc[mi][ni][3] - mn1));
                rs0 += __low2float(h0) + __high2float(h0);
                rs1 += __low2float(h1) + __high2float(h1);
                Ps[(r0    ) * QSTW + 4 * ni + tig] = *(unsigned*)&h0;
                Ps[(r0 + 8) * QSTW + 4 * ni + tig] = *(unsigned*)&h1;
            }
            rs0 += __shfl_xor_sync(0xffffffffu, rs0, 1);
            rs0 += __shfl_xor_sync(0xffffffffu, rs0, 2);
            rs1 += __shfl_xor_sync(0xffffffffu, rs1, 1);
            rs1 += __shfl_xor_sync(0xffffffffu, rs1, 2);

            lrow[mi * 2 + 0] = lrow[mi * 2 + 0] * corr0 + rs0;
            lrow[mi * 2 + 1] = lrow[mi * 2 + 1] * corr1 + rs1;
            mrow[mi * 2 + 0] = mn0; mrow[mi * 2 + 1] = mn1;

            #pragma unroll
            for (int ni = 0; ni < 8; ni++) {
                oacc[mi][ni][0] *= corr0; oacc[mi][ni][1] *= corr0;
                oacc[mi][ni][2] *= corr1; oacc[mi][ni][3] *= corr1;
            }
        }
        __syncwarp();

        // ---- O += P V : 4 k-steps of 16 (key dim), 2 row-tiles ----
        #pragma unroll
        for (int ksi = 0; ksi < 4; ksi++) {
            int kw = ksi * 8;
            unsigned ap[2][4];
            #pragma unroll
            for (int mi = 0; mi < 2; mi++) {
                int r0 = rbase + mi * 16;
                ap[mi][0] = Ps[(r0    ) * QSTW + kw + tig];
                ap[mi][1] = Ps[(r0 + 8) * QSTW + kw + tig];
                ap[mi][2] = Ps[(r0    ) * QSTW + kw + 4 + tig];
                ap[mi][3] = Ps[(r0 + 8) * QSTW + kw + 4 + tig];
            }
            #pragma unroll
            for (int ni = 0; ni < 8; ni++) {
                int n = ni * 8 + g;
                unsigned b0 = Vs[(kw + tig)     * VSTW + n];
                unsigned b1 = Vs[(kw + 4 + tig) * VSTW + n];
                #pragma unroll
                for (int mi = 0; mi < 2; mi++)
                    mma_f16(oacc[mi][ni], ap[mi][0], ap[mi][1], ap[mi][2], ap[mi][3], b0, b1);
            }
        }
        __syncwarp();
    }

    #pragma unroll
    for (int mi = 0; mi < 2; mi++) {
        float inv0 = 1.0f / lrow[mi * 2 + 0];
        float inv1 = 1.0f / lrow[mi * 2 + 1];
        size_t row0 = (size_t)(b * Tq + qb * 128 + rbase + mi * 16);
        size_t row1 = row0 + 8;
        #pragma unroll
        for (int ni = 0; ni < 8; ni++) {
            int col = h * HDq + ni * 8 + 2 * tig;
            *(__half2*)&y[row0 * Dq + col] =
                __floats2half2_rn(oacc[mi][ni][0] * inv0, oacc[mi][ni][1] * inv0);
            *(__half2*)&y[row1 * Dq + col] =
                __floats2half2_rn(oacc[mi][ni][2] * inv1, oacc[mi][ni][3] * inv1);
        }
    }
}

// ---------------------------------------------------------------------------
// Launch
// ---------------------------------------------------------------------------
extern "C" void kernel_launch(void* const* d_in, const int* in_sizes, int n_in,
                              void* d_out, int out_size) {
    const int*   idx     = (const int*)  d_in[0];
    const float* tok_emb = (const float*)d_in[1];
    const float* ln1_s   = (const float*)d_in[2];
    const float* ln1_b   = (const float*)d_in[3];
    const float* qkv_w   = (const float*)d_in[4];
    const float* qkv_b   = (const float*)d_in[5];
    const float* out_w   = (const float*)d_in[6];
    const float* out_b   = (const float*)d_in[7];
    const float* ln2_s   = (const float*)d_in[8];
    const float* ln2_b   = (const float*)d_in[9];
    const float* mlp_w1  = (const float*)d_in[10];
    const float* mlp_b1  = (const float*)d_in[11];
    const float* mlp_w2  = (const float*)d_in[12];
    const float* mlp_b2  = (const float*)d_in[13];
    const float* lnf_s   = (const float*)d_in[14];
    const float* lnf_b   = (const float*)d_in[15];
    const float* head_w  = (const float*)d_in[16];
    float* logits = (float*)d_out;

    float *x;
    __half *qkvh, *lnh, *yh, *ffh;
    __half2 *wqkv, *wout, *wm1, *wm2, *whd;
    cudaGetSymbolAddress((void**)&x,    g_x);
    cudaGetSymbolAddress((void**)&qkvh, g_qkvh);
    cudaGetSymbolAddress((void**)&lnh,  g_lnh);
    cudaGetSymbolAddress((void**)&yh,   g_yh);
    cudaGetSymbolAddress((void**)&ffh,  g_ffh);
    cudaGetSymbolAddress((void**)&wqkv, g_wqkv_h);
    cudaGetSymbolAddress((void**)&wout, g_wout_h);
    cudaGetSymbolAddress((void**)&wm1,  g_wm1_h);
    cudaGetSymbolAddress((void**)&wm2,  g_wm2_h);
    cudaGetSymbolAddress((void**)&whd,  g_whd_h);

    // smem: BMt=128 -> 3*(2048+2048)*4 = 48 KB ; BMt=64 -> 36 KB
    const int smem128 = 3 * (128 * 16 + 16 * 128) * (int)sizeof(unsigned);
    const int smem64  = 3 * ( 64 * 16 + 16 * 128) * (int)sizeof(unsigned);
    cudaFuncSetAttribute((const void*)hgemm_kernel<0, 128>,
                         cudaFuncAttributeMaxDynamicSharedMemorySize, smem128);
    cudaFuncSetAttribute((const void*)hgemm_kernel<2, 128>,
                         cudaFuncAttributeMaxDynamicSharedMemorySize, smem128);
    cudaFuncSetAttribute((const void*)hgemm_kernel<3, 128>,
                         cudaFuncAttributeMaxDynamicSharedMemorySize, smem128);
    cudaFuncSetAttribute((const void*)hgemm_kernel<1, 64>,
                         cudaFuncAttributeMaxDynamicSharedMemorySize, smem64);
    // attention smem: (128+64+128)*36 + 32*72 = 13824 words = 55.3 KB
    const int attn_smem = (320 * QSTW + 32 * VSTW) * (int)sizeof(unsigned);
    cudaFuncSetAttribute(attn5_kernel,
                         cudaFuncAttributeMaxDynamicSharedMemorySize, attn_smem);

    // weight convert: fp32 [K][N] -> half2 [K/2][N]; 3D grid (n4, k2, layer)
    auto cvt = [](const float* src, __half2* dst, int K, int N, int L) {
        int n4 = N / 4;
        dim3 grid((n4 + 255) / 256, K / 2, L);
        w2h4_kernel<<<grid, 256>>>((const float4*)src, (uint4*)dst, K, N);
    };
    cvt(qkv_w,  wqkv, Dq,  3 * Dq, Lq);
    cvt(out_w,  wout, Dq,  Dq,     Lq);
    cvt(mlp_w1, wm1,  Dq,  FFq,    Lq);
    cvt(mlp_w2, wm2,  FFq, Dq,     Lq);
    cvt(head_w, whd,  Dq,  Vq,     1);

    embed_kernel<<<Rq, 256>>>(idx, tok_emb, x);

    for (int l = 0; l < Lq; l++) {
        ln_kernel<<<Rq / 8, 256>>>(x, ln1_s + (size_t)l * Dq, ln1_b + (size_t)l * Dq, lnh);
        // qkv: N=3072, fp16 output (EPI 3)
        hgemm_kernel<3, 128><<<dim3(3 * Dq / 128, Rq / 128), 128, smem128>>>(
            lnh, wqkv + (size_t)l * (Dq / 2) * 3 * Dq, qkv_b + (size_t)l * 3 * Dq,
            (float*)qkvh, Rq, 3 * Dq, Dq);
        attn5_kernel<<<dim3(Tq / 128, Hq, Bq), 128, attn_smem>>>(qkvh, yh);
        // out-proj: N=1024, BMt=64, += residual
        hgemm_kernel<1, 64><<<dim3(Dq / 128, Rq / 64), 128, smem64>>>(
            yh, wout + (size_t)l * (Dq / 2) * Dq, out_b + (size_t)l * Dq,
            x, Rq, Dq, Dq);
        ln_kernel<<<Rq / 8, 256>>>(x, ln2_s + (size_t)l * Dq, ln2_b + (size_t)l * Dq, lnh);
        // mlp1: N=4096, gelu -> fp16 ff
        hgemm_kernel<2, 128><<<dim3(FFq / 128, Rq / 128), 128, smem128>>>(
            lnh, wm1 + (size_t)l * (Dq / 2) * FFq, mlp_b1 + (size_t)l * FFq,
            (float*)ffh, Rq, FFq, Dq);
        // mlp2: N=1024, K=4096, BMt=64, += residual
        hgemm_kernel<1, 64><<<dim3(Dq / 128, Rq / 64), 128, smem64>>>(
            ffh, wm2 + (size_t)l * (FFq / 2) * Dq, mlp_b2 + (size_t)l * Dq,
            x, Rq, Dq, FFq);
    }

    ln_kernel<<<Rq / 8, 256>>>(x, lnf_s, lnf_b, lnh);
    // head: N=32000
    hgemm_kernel<0, 128><<<dim3(Vq / 128, Rq / 128), 128, smem128>>>(
        lnh, whd, (const float*)nullptr, logits, Rq, Vq, Dq);
}

// round 17
// speedup vs baseline: 1.0040x; 1.0040x over previous
#include <cuda_runtime.h>
#include <cuda_fp16.h>
#include <cstdint>
#include <math.h>
#include <math_constants.h>

// Problem constants
#define Bq  2
#define Tq  1024
#define Dq  1024
#define Hq  16
#define FFq 4096
#define Lq  8
#define Vq  32000
#define HDq 64
#define Rq  (Bq * Tq)   // 2048 rows

// ---------------------------------------------------------------------------
// Scratch (device globals; no runtime allocation allowed)
// ---------------------------------------------------------------------------
__device__ float  g_x   [Rq * Dq];       // residual stream (fp32)
__device__ __half g_qkvh[Rq * 3 * Dq];   // q|k|v (fp16)
__device__ __half g_lnh [Rq * Dq];       // layernorm output (fp16 GEMM A)
__device__ __half g_yh  [Rq * Dq];       // attention output (fp16 GEMM A)
__device__ __half g_ffh [Rq * FFq];      // mlp hidden (fp16 GEMM A)

// k-pair-interleaved half2 weights: [K/2][N], elem = (w[2k2][n], w[2k2+1][n])
__device__ __half2 g_wqkv_h[Lq * (Dq/2) * 3 * Dq];
__device__ __half2 g_wout_h[Lq * (Dq/2) * Dq];
__device__ __half2 g_wm1_h [Lq * (Dq/2) * FFq];
__device__ __half2 g_wm2_h [Lq * (FFq/2) * Dq];
__device__ __half2 g_whd_h [(Dq/2) * Vq];

// ---------------------------------------------------------------------------
// Weight convert: fp32 [K][N] -> half2 [K/2][N], 3D grid (n4, k2, layer).
// Reads are single-use: stream them (evict-first) to spare L2.
// ---------------------------------------------------------------------------
__global__ void w2h4_kernel(const float4* __restrict__ in,
                            uint4* __restrict__ out, int K, int N) {
    int n4 = blockIdx.x * blockDim.x + threadIdx.x;   // float4 column index
    int N4 = N >> 2;
    if (n4 >= N4) return;
    int k2 = blockIdx.y;
    size_t lbase = (size_t)blockIdx.z * K * N4;       // in float4 units
    float4 a = __ldcs(&in[lbase + (size_t)(2 * k2)     * N4 + n4]);
    float4 b = __ldcs(&in[lbase + (size_t)(2 * k2 + 1) * N4 + n4]);
    __half2 h0 = __floats2half2_rn(a.x, b.x);
    __half2 h1 = __floats2half2_rn(a.y, b.y);
    __half2 h2 = __floats2half2_rn(a.z, b.z);
    __half2 h3 = __floats2half2_rn(a.w, b.w);
    uint4 u;
    u.x = *(unsigned*)&h0; u.y = *(unsigned*)&h1;
    u.z = *(unsigned*)&h2; u.w = *(unsigned*)&h3;
    out[(size_t)blockIdx.z * (K / 2) * N4 + (size_t)k2 * N4 + n4] = u;
}

// ---------------------------------------------------------------------------
__global__ void embed_kernel(const int* __restrict__ idx,
                             const float* __restrict__ emb,
                             float* __restrict__ x) {
    int row = blockIdx.x;
    int t   = row % Tq;
    int tok = idx[row];
    const float* er = emb + (size_t)tok * Dq;
    const float neg_log = -logf(10000.0f) / (float)Dq;
    for (int d = threadIdx.x; d < Dq; d += blockDim.x) {
        int i2 = d & ~1;
        float freq = expf(neg_log * (float)i2);
        float ang  = (float)t * freq;
        float pe   = (d & 1) ? cosf(ang) : sinf(ang);
        x[(size_t)row * Dq + d] = er[d] + pe;
    }
}

// ---------------------------------------------------------------------------
// Warp-per-row LayerNorm (no smem, shfl-only reductions); writes fp16.
// ---------------------------------------------------------------------------
__global__ __launch_bounds__(256)
void ln_kernel(const float* __restrict__ x,
               const float* __restrict__ sc,
               const float* __restrict__ bi,
               __half* __restrict__ out) {
    int lane = threadIdx.x & 31;
    int w    = threadIdx.x >> 5;
    int row  = blockIdx.x * 8 + w;
    const float4* xr = (const float4*)(x + (size_t)row * Dq);

    float4 v[8];
    float s = 0.0f;
    #pragma unroll
    for (int i = 0; i < 8; i++) {
        v[i] = xr[lane + i * 32];
        s += v[i].x + v[i].y + v[i].z + v[i].w;
    }
    #pragma unroll
    for (int o = 16; o; o >>= 1) s += __shfl_xor_sync(0xffffffffu, s, o);
    float mean = s * (1.0f / (float)Dq);

    float q = 0.0f;
    #pragma unroll
    for (int i = 0; i < 8; i++) {
        float dx = v[i].x - mean, dy = v[i].y - mean;
        float dz = v[i].z - mean, dw = v[i].w - mean;
        q += dx * dx + dy * dy + dz * dz + dw * dw;
    }
    #pragma unroll
    for (int o = 16; o; o >>= 1) q += __shfl_xor_sync(0xffffffffu, q, o);
    float inv = rsqrtf(q * (1.0f / (float)Dq) + 1e-5f);

    #pragma unroll
    for (int i = 0; i < 8; i++) {
        int c = (lane + i * 32) * 4;
        float o0 = (v[i].x - mean) * inv * sc[c + 0] + bi[c + 0];
        float o1 = (v[i].y - mean) * inv * sc[c + 1] + bi[c + 1];
        float o2 = (v[i].z - mean) * inv * sc[c + 2] + bi[c + 2];
        float o3 = (v[i].w - mean) * inv * sc[c + 3] + bi[c + 3];
        __half2 h0 = __floats2half2_rn(o0, o1);
        __half2 h1 = __floats2half2_rn(o2, o3);
        uint2 u;
        u.x = *(unsigned*)&h0; u.y = *(unsigned*)&h1;
        *(uint2*)(out + (size_t)row * Dq + c) = u;
    }
}

// ---------------------------------------------------------------------------
// FP16 tensor-core GEMM (m16n8k16, fp32 accum), 3-stage cp.async ring, BK=32.
// (exact R10/R14 pipeline — proven; at the legacy-HMMA issue ceiling)
//   EPI 0: C(fp32) = AB + bias ; EPI 1: C(fp32) += AB + bias
//   EPI 2: C(fp16) = gelu(AB + bias) ; EPI 3: C(fp16) = AB + bias
// ---------------------------------------------------------------------------
__device__ __forceinline__ void mma_f16(float c[4],
                                        unsigned a0, unsigned a1, unsigned a2, unsigned a3,
                                        unsigned b0, unsigned b1) {
    asm volatile(
        "mma.sync.aligned.m16n8k16.row.col.f32.f16.f16.f32 "
        "{%0,%1,%2,%3}, {%4,%5,%6,%7}, {%8,%9}, {%0,%1,%2,%3};"
        : "+f"(c[0]), "+f"(c[1]), "+f"(c[2]), "+f"(c[3])
        : "r"(a0), "r"(a1), "r"(a2), "r"(a3), "r"(b0), "r"(b1));
}

#define CP16(dst, src) \
    asm volatile("cp.async.cg.shared.global [%0], [%1], 16;\n" :: "r"(dst), "l"(src))

template <int EPI, int BMt>
__global__ __launch_bounds__(128)
void hgemm_kernel(const __half* __restrict__ A, const __half2* __restrict__ B2,
                  const float* __restrict__ bias, float* __restrict__ C,
                  int M, int N, int K) {
    constexpr int BK = 32;
    constexpr int ASZW = BMt * 16;
    constexpr int BSZW = 16 * 128;
    constexpr int STG  = ASZW + BSZW;
    constexpr int MI   = BMt / 32;
    extern __shared__ unsigned smw[];

    int tid  = threadIdx.x;
    int lane = tid & 31;
    int warp = tid >> 5;
    int g    = lane >> 2;
    int tig  = lane & 3;
    int wm   = warp & 1;
    int wn   = warp >> 1;
    int rm   = wm * (BMt / 2);
    int cn   = wn * 64;

    const __half*  Ab  = A + (size_t)(blockIdx.y * BMt) * K;
    const __half2* Bb2 = B2 + (size_t)blockIdx.x * 128;

    float acc[MI][8][4];
    #pragma unroll
    for (int mi = 0; mi < MI; mi++)
        #pragma unroll
        for (int ni = 0; ni < 8; ni++)
            #pragma unroll
            for (int c = 0; c < 4; c++) acc[mi][ni][c] = 0.0f;

    unsigned sBase = (unsigned)__cvta_generic_to_shared(smw);

    auto issue = [&](int kt, int p) {
        unsigned sa = sBase + (unsigned)(p * STG) * 4u;
        unsigned sb = sa + (unsigned)ASZW * 4u;
        #pragma unroll
        for (int i = 0; i < BMt / 32; i++) {
            int lin = tid + i * 128;
            int m = lin >> 2, c = lin & 3;
            const __half* src = Ab + (size_t)m * K + kt + c * 8;
            unsigned dst = sa + (unsigned)(m * 16 + ((c ^ ((m >> 1) & 3)) << 2)) * 4u;
            CP16(dst, src);
        }
        #pragma unroll
        for (int i = 0; i < 4; i++) {
            int lin = tid + i * 128;
            int k2 = lin >> 5, c4 = lin & 31;
            const __half2* src = Bb2 + (size_t)(kt / 2 + k2) * N + c4 * 4;
            unsigned dst = sb + (unsigned)(k2 * 128 + ((c4 ^ (2 * (k2 & 3))) << 2)) * 4u;
            CP16(dst, src);
        }
        asm volatile("cp.async.commit_group;\n");
    };

    int ntiles = K / BK;
    issue(0, 0);
    issue(BK, 1);

    for (int t = 0; t < ntiles; t++) {
        int p = t % 3;
        asm volatile("cp.async.wait_group 1;\n");
        __syncthreads();
        if (t + 2 < ntiles) {
            issue((t + 2) * BK, (t + 2) % 3);
        } else {
            asm volatile("cp.async.commit_group;\n");
        }

        const unsigned* Ap = smw + p * STG;
        const unsigned* Bp = Ap + ASZW;
        #pragma unroll
        for (int ksi = 0; ksi < 2; ksi++) {
            unsigned af[MI][4], bf[8][2];
            #pragma unroll
            for (int mi = 0; mi < MI; mi++) {
                int m1 = rm + mi * 16 + g;
                int m2 = m1 + 8;
                unsigned s1 = (unsigned)((m1 >> 1) & 3);
                unsigned s2 = (unsigned)((m2 >> 1) & 3);
                unsigned c0 = (unsigned)(2 * ksi);
                af[mi][0] = Ap[m1 * 16 + (((c0    ) ^ s1) << 2) + tig];
                af[mi][1] = Ap[m2 * 16 + (((c0    ) ^ s2) << 2) + tig];
                af[mi][2] = Ap[m1 * 16 + (((c0 + 1) ^ s1) << 2) + tig];
                af[mi][3] = Ap[m2 * 16 + (((c0 + 1) ^ s2) << 2) + tig];
            }
            int k2b = ksi * 8;
            #pragma unroll
            for (int ni = 0; ni < 8; ni++) {
                unsigned nb = (unsigned)(cn + ni * 8 + g);
                bf[ni][0] = Bp[(k2b + tig)     * 128 + (nb ^ (unsigned)(8 * tig))];
                bf[ni][1] = Bp[(k2b + tig + 4) * 128 + (nb ^ (unsigned)(8 * tig))];
            }
            #pragma unroll
            for (int mi = 0; mi < MI; mi++)
                #pragma unroll
                for (int ni = 0; ni < 8; ni++)
                    mma_f16(acc[mi][ni],
                            af[mi][0], af[mi][1], af[mi][2], af[mi][3],
                            bf[ni][0], bf[ni][1]);
        }
        __syncthreads();
    }

    #pragma unroll
    for (int ni = 0; ni < 8; ni++) {
        int gc = blockIdx.x * 128 + cn + ni * 8 + 2 * tig;
        float bv0 = bias ? bias[gc]     : 0.0f;
        float bv1 = bias ? bias[gc + 1] : 0.0f;
        #pragma unroll
        for (int mi = 0; mi < MI; mi++) {
            int gr1 = blockIdx.y * BMt + rm + mi * 16 + g;
            int gr2 = gr1 + 8;
            float v00 = acc[mi][ni][0] + bv0;
            float v01 = acc[mi][ni][1] + bv1;
            float v10 = acc[mi][ni][2] + bv0;
            float v11 = acc[mi][ni][3] + bv1;
            if (EPI == 0) {
                *(float2*)(C + (size_t)gr1 * N + gc) = make_float2(v00, v01);
                *(float2*)(C + (size_t)gr2 * N + gc) = make_float2(v10, v11);
            } else if (EPI == 1) {
                float2* p1 = (float2*)(C + (size_t)gr1 * N + gc);
                float2* p2 = (float2*)(C + (size_t)gr2 * N + gc);
                float2 o1 = *p1, o2 = *p2;
                *p1 = make_float2(o1.x + v00, o1.y + v01);
                *p2 = make_float2(o2.x + v10, o2.y + v11);
            } else if (EPI == 2) {
                const float is2 = 0.70710678118654752f;
                __half* Ch = (__half*)C;
                float g00 = 0.5f * v00 * (1.0f + erff(v00 * is2));
                float g01 = 0.5f * v01 * (1.0f + erff(v01 * is2));
                float g10 = 0.5f * v10 * (1.0f + erff(v10 * is2));
                float g11 = 0.5f * v11 * (1.0f + erff(v11 * is2));
                *(__half2*)(Ch + (size_t)gr1 * N + gc) = __floats2half2_rn(g00, g01);
                *(__half2*)(Ch + (size_t)gr2 * N + gc) = __floats2half2_rn(g10, g11);
            } else {
                __half* Ch = (__half*)C;
                *(__half2*)(Ch + (size_t)gr1 * N + gc) = __floats2half2_rn(v00, v01);
                *(__half2*)(Ch + (size_t)gr2 * N + gc) = __floats2half2_rn(v10, v11);
            }
        }
    }
}

// ---------------------------------------------------------------------------
// FP16 tensor-core flash attention (m16n8k16), fp16 qkv input (raw staging).
// One CTA per (64q, head, batch); 4 warps. (proven R14 version)
// Smem (half2 words): Q/K/P rows stride 36; V k-pair-interleaved stride 72.
// ---------------------------------------------------------------------------
#define QSTW 36
#define VSTW 72

__global__ __launch_bounds__(128)
void attn4_kernel(const __half* __restrict__ qkv, __half* __restrict__ y) {
    extern __shared__ unsigned smA[];
    unsigned* Qs = smA;                    // [64][36]
    unsigned* Ks = Qs + 64 * QSTW;         // [64][36]
    unsigned* Ps = Ks + 64 * QSTW;         // [64][36]
    unsigned* Vs = Ps + 64 * QSTW;         // [32][72]

    int qb = blockIdx.x, h = blockIdx.y, b = blockIdx.z;
    int tid = threadIdx.x;
    int lane = tid & 31, w = tid >> 5;
    int g = lane >> 2, tig = lane & 3;

    const size_t rs = 3 * Dq;              // halves
    const __half* qbase = qkv + ((size_t)(b * Tq + qb * 64)) * rs + h * HDq;
    const __half2 sc2 = __half2half2(__float2half(0.125f));  // exact pow2

    // stage Q: 64 rows x 64 halves = 512 x 16B chunks
    #pragma unroll
    for (int i = 0; i < 4; i++) {
        int lin = tid + i * 128;
        int r = lin >> 3, c = lin & 7;
        uint4 u = *(const uint4*)(qbase + (size_t)r * rs + c * 8);
        __half2* hp = (__half2*)&u;
        hp[0] = __hmul2(hp[0], sc2); hp[1] = __hmul2(hp[1], sc2);
        hp[2] = __hmul2(hp[2], sc2); hp[3] = __hmul2(hp[3], sc2);
        *(uint4*)&Qs[r * QSTW + c * 4] = u;
    }

    float oacc[8][4];
    #pragma unroll
    for (int ni = 0; ni < 8; ni++)
        #pragma unroll
        for (int c = 0; c < 4; c++) oacc[ni][c] = 0.0f;
    float mrow0 = -CUDART_INF_F, mrow1 = -CUDART_INF_F;
    float lrow0 = 0.0f, lrow1 = 0.0f;

    int rloc0 = w * 16 + g;
    int rloc1 = rloc0 + 8;

    for (int kt = 0; kt <= qb; kt++) {
        __syncthreads();
        const __half* kbase = qkv + ((size_t)(b * Tq + kt * 64)) * rs + Dq + h * HDq;
        const __half* vbase = kbase + Dq;
        // stage K: raw 16B copies
        #pragma unroll
        for (int i = 0; i < 4; i++) {
            int lin = tid + i * 128;
            int r = lin >> 3, c = lin & 7;
            uint4 u = *(const uint4*)(kbase + (size_t)r * rs + c * 8);
            *(uint4*)&Ks[r * QSTW + c * 4] = u;
        }
        // stage V: pair-gather (V[2k2][n], V[2k2+1][n]) via lows/highs
        #pragma unroll
        for (int i = 0; i < 4; i++) {
            int lin = tid + i * 128;
            int k2 = lin >> 4, q = lin & 15;
            uint2 a2 = *(const uint2*)(vbase + (size_t)(2 * k2)     * rs + q * 4);
            uint2 b2 = *(const uint2*)(vbase + (size_t)(2 * k2 + 1) * rs + q * 4);
            __half2 ax = *(__half2*)&a2.x, ay = *(__half2*)&a2.y;
            __half2 bx = *(__half2*)&b2.x, by = *(__half2*)&b2.y;
            __half2 w0 = __lows2half2(ax, bx),  w1 = __highs2half2(ax, bx);
            __half2 w2 = __lows2half2(ay, by),  w3 = __highs2half2(ay, by);
            uint4 u;
            u.x = *(unsigned*)&w0; u.y = *(unsigned*)&w1;
            u.z = *(unsigned*)&w2; u.w = *(unsigned*)&w3;
            *(uint4*)&Vs[k2 * VSTW + q * 4] = u;
        }
        __syncthreads();

        // ---- S = Q K^T : 4 k-steps of 16 ----
        float sacc[8][4];
        #pragma unroll
        for (int ni = 0; ni < 8; ni++)
            #pragma unroll
            for (int c = 0; c < 4; c++) sacc[ni][c] = 0.0f;
        #pragma unroll
        for (int ksi = 0; ksi < 4; ksi++) {
            int kw = ksi * 8;
            unsigned a0 = Qs[rloc0 * QSTW + kw + tig];
            unsigned a1 = Qs[rloc1 * QSTW + kw + tig];
            unsigned a2 = Qs[rloc0 * QSTW + kw + 4 + tig];
            unsigned a3 = Qs[rloc1 * QSTW + kw + 4 + tig];
            #pragma unroll
            for (int ni = 0; ni < 8; ni++) {
                int nr = ni * 8 + g;
                unsigned b0 = Ks[nr * QSTW + kw + tig];
                unsigned b1 = Ks[nr * QSTW + kw + 4 + tig];
                mma_f16(sacc[ni], a0, a1, a2, a3, b0, b1);
            }
        }

        // ---- causal mask on diagonal tile ----
        if (kt == qb) {
            #pragma unroll
            for (int ni = 0; ni < 8; ni++) {
                int c0 = ni * 8 + 2 * tig, c1 = c0 + 1;
                if (c0 > rloc0) sacc[ni][0] = -CUDART_INF_F;
                if (c1 > rloc0) sacc[ni][1] = -CUDART_INF_F;
                if (c0 > rloc1) sacc[ni][2] = -CUDART_INF_F;
                if (c1 > rloc1) sacc[ni][3] = -CUDART_INF_F;
            }
        }

        // ---- online softmax ----
        float mx0 = -CUDART_INF_F, mx1 = -CUDART_INF_F;
        #pragma unroll
        for (int ni = 0; ni < 8; ni++) {
            mx0 = fmaxf(mx0, fmaxf(sacc[ni][0], sacc[ni][1]));
            mx1 = fmaxf(mx1, fmaxf(sacc[ni][2], sacc[ni][3]));
        }
        mx0 = fmaxf(mx0, __shfl_xor_sync(0xffffffffu, mx0, 1));
        mx0 = fmaxf(mx0, __shfl_xor_sync(0xffffffffu, mx0, 2));
        mx1 = fmaxf(mx1, __shfl_xor_sync(0xffffffffu, mx1, 1));
        mx1 = fmaxf(mx1, __shfl_xor_sync(0xffffffffu, mx1, 2));

        float mn0 = fmaxf(mrow0, mx0);
        float mn1 = fmaxf(mrow1, mx1);
        float corr0 = __expf(mrow0 - mn0);
        float corr1 = __expf(mrow1 - mn1);

        float rs0 = 0.0f, rs1 = 0.0f;
        #pragma unroll
        for (int ni = 0; ni < 8; ni++) {
            __half2 h0 = __floats2half2_rn(__expf(sacc[ni][0] - mn0),
                                           __expf(sacc[ni][1] - mn0));
            __half2 h1 = __floats2half2_rn(__expf(sacc[ni][2] - mn1),
                                           __expf(sacc[ni][3] - mn1));
            rs0 += __low2float(h0) + __high2float(h0);
            rs1 += __low2float(h1) + __high2float(h1);
            Ps[rloc0 * QSTW + 4 * ni + tig] = *(unsigned*)&h0;
            Ps[rloc1 * QSTW + 4 * ni + tig] = *(unsigned*)&h1;
        }
        rs0 += __shfl_xor_sync(0xffffffffu, rs0, 1);
        rs0 += __shfl_xor_sync(0xffffffffu, rs0, 2);
        rs1 += __shfl_xor_sync(0xffffffffu, rs1, 1);
        rs1 += __shfl_xor_sync(0xffffffffu, rs1, 2);

        lrow0 = lrow0 * corr0 + rs0;
        lrow1 = lrow1 * corr1 + rs1;
        mrow0 = mn0; mrow1 = mn1;

        #pragma unroll
        for (int ni = 0; ni < 8; ni++) {
            oacc[ni][0] *= corr0; oacc[ni][1] *= corr0;
            oacc[ni][2] *= corr1; oacc[ni][3] *= corr1;
        }
        __syncwarp();

        // ---- O += P V : 4 k-steps of 16 (key dim) ----
        #pragma unroll
        for (int ksi = 0; ksi < 4; ksi++) {
            int kw = ksi * 8;
            unsigned a0 = Ps[rloc0 * QSTW + kw + tig];
            unsigned a1 = Ps[rloc1 * QSTW + kw + tig];
            unsigned a2 = Ps[rloc0 * QSTW + kw + 4 + tig];
            unsigned a3 = Ps[rloc1 * QSTW + kw + 4 + tig];
            #pragma unroll
            for (int ni = 0; ni < 8; ni++) {
                int n = ni * 8 + g;
                unsigned b0 = Vs[(kw + tig)     * VSTW + n];
                unsigned b1 = Vs[(kw + 4 + tig) * VSTW + n];
                mma_f16(oacc[ni], a0, a1, a2, a3, b0, b1);
            }
        }
        __syncwarp();
    }

    float inv0 = 1.0f / lrow0;
    float inv1 = 1.0f / lrow1;
    size_t row0 = (size_t)(b * Tq + qb * 64 + rloc0);
    size_t row1 = row0 + 8;
    #pragma unroll
    for (int ni = 0; ni < 8; ni++) {
        int col = h * HDq + ni * 8 + 2 * tig;
        *(__half2*)&y[row0 * Dq + col] =
            __floats2half2_rn(oacc[ni][0] * inv0, oacc[ni][1] * inv0);
        *(__half2*)&y[row1 * Dq + col] =
            __floats2half2_rn(oacc[ni][2] * inv1, oacc[ni][3] * inv1);
    }
}

// ---------------------------------------------------------------------------
// Launch
// ---------------------------------------------------------------------------
extern "C" void kernel_launch(void* const* d_in, const int* in_sizes, int n_in,
                              void* d_out, int out_size) {
    const int*   idx     = (const int*)  d_in[0];
    const float* tok_emb = (const float*)d_in[1];
    const float* ln1_s   = (const float*)d_in[2];
    const float* ln1_b   = (const float*)d_in[3];
    const float* qkv_w   = (const float*)d_in[4];
    const float* qkv_b   = (const float*)d_in[5];
    const float* out_w   = (const float*)d_in[6];
    const float* out_b   = (const float*)d_in[7];
    const float* ln2_s   = (const float*)d_in[8];
    const float* ln2_b   = (const float*)d_in[9];
    const float* mlp_w1  = (const float*)d_in[10];
    const float* mlp_b1  = (const float*)d_in[11];
    const float* mlp_w2  = (const float*)d_in[12];
    const float* mlp_b2  = (const float*)d_in[13];
    const float* lnf_s   = (const float*)d_in[14];
    const float* lnf_b   = (const float*)d_in[15];
    const float* head_w  = (const float*)d_in[16];
    float* logits = (float*)d_out;

    float *x;
    __half *qkvh, *lnh, *yh, *ffh;
    __half2 *wqkv, *wout, *wm1, *wm2, *whd;
    cudaGetSymbolAddress((void**)&x,    g_x);
    cudaGetSymbolAddress((void**)&qkvh, g_qkvh);
    cudaGetSymbolAddress((void**)&lnh,  g_lnh);
    cudaGetSymbolAddress((void**)&yh,   g_yh);
    cudaGetSymbolAddress((void**)&ffh,  g_ffh);
    cudaGetSymbolAddress((void**)&wqkv, g_wqkv_h);
    cudaGetSymbolAddress((void**)&wout, g_wout_h);
    cudaGetSymbolAddress((void**)&wm1,  g_wm1_h);
    cudaGetSymbolAddress((void**)&wm2,  g_wm2_h);
    cudaGetSymbolAddress((void**)&whd,  g_whd_h);

    // smem: BMt=128 -> 3*(2048+2048)*4 = 48 KB ; BMt=64 -> 36 KB
    const int smem128 = 3 * (128 * 16 + 16 * 128) * (int)sizeof(unsigned);
    const int smem64  = 3 * ( 64 * 16 + 16 * 128) * (int)sizeof(unsigned);
    cudaFuncSetAttribute((const void*)hgemm_kernel<0, 128>,
                         cudaFuncAttributeMaxDynamicSharedMemorySize, smem128);
    cudaFuncSetAttribute((const void*)hgemm_kernel<2, 128>,
                         cudaFuncAttributeMaxDynamicSharedMemorySize, smem128);
    cudaFuncSetAttribute((const void*)hgemm_kernel<3, 128>,
                         cudaFuncAttributeMaxDynamicSharedMemorySize, smem128);
    cudaFuncSetAttribute((const void*)hgemm_kernel<1, 64>,
                         cudaFuncAttributeMaxDynamicSharedMemorySize, smem64);
    const int attn_smem = (3 * 64 * QSTW + 32 * VSTW) * (int)sizeof(unsigned); // 36 KB
    cudaFuncSetAttribute(attn4_kernel,
                         cudaFuncAttributeMaxDynamicSharedMemorySize, attn_smem);

    // weight convert: fp32 [K][N] -> half2 [K/2][N]; 3D grid (n4, k2, layer)
    auto cvt = [](const float* src, __half2* dst, int K, int N, int L) {
        int n4 = N / 4;
        dim3 grid((n4 + 255) / 256, K / 2, L);
        w2h4_kernel<<<grid, 256>>>((const float4*)src, (uint4*)dst, K, N);
    };
    cvt(qkv_w,  wqkv, Dq,  3 * Dq, Lq);
    cvt(out_w,  wout, Dq,  Dq,     Lq);
    cvt(mlp_w1, wm1,  Dq,  FFq,    Lq);
    cvt(mlp_w2, wm2,  FFq, Dq,     Lq);
    cvt(head_w, whd,  Dq,  Vq,     1);

    embed_kernel<<<Rq, 256>>>(idx, tok_emb, x);

    for (int l = 0; l < Lq; l++) {
        ln_kernel<<<Rq / 8, 256>>>(x, ln1_s + (size_t)l * Dq, ln1_b + (size_t)l * Dq, lnh);
        // qkv: N=3072, fp16 output (EPI 3)
        hgemm_kernel<3, 128><<<dim3(3 * Dq / 128, Rq / 128), 128, smem128>>>(
            lnh, wqkv + (size_t)l * (Dq / 2) * 3 * Dq, qkv_b + (size_t)l * 3 * Dq,
            (float*)qkvh, Rq, 3 * Dq, Dq);
        attn4_kernel<<<dim3(Tq / 64, Hq, Bq), 128, attn_smem>>>(qkvh, yh);
        // out-proj: N=1024, BMt=64, += residual
        hgemm_kernel<1, 64><<<dim3(Dq / 128, Rq / 64), 128, smem64>>>(
            yh, wout + (size_t)l * (Dq / 2) * Dq, out_b + (size_t)l * Dq,
            x, Rq, Dq, Dq);
        ln_kernel<<<Rq / 8, 256>>>(x, ln2_s + (size_t)l * Dq, ln2_b + (size_t)l * Dq, lnh);
        // mlp1: N=4096, gelu -> fp16 ff
        hgemm_kernel<2, 128><<<dim3(FFq / 128, Rq / 128), 128, smem128>>>(
            lnh, wm1 + (size_t)l * (Dq / 2) * FFq, mlp_b1 + (size_t)l * FFq,
            (float*)ffh, Rq, FFq, Dq);
        // mlp2: N=1024, K=4096, BMt=64, += residual
        hgemm_kernel<1, 64><<<dim3(Dq / 128, Rq / 64), 128, smem64>>>(
            ffh, wm2 + (size_t)l * (FFq / 2) * Dq, mlp_b2 + (size_t)l * Dq,
            x, Rq, Dq, FFq);
    }

    ln_kernel<<<Rq / 8, 256>>>(x, lnf_s, lnf_b, lnh);
    // head: N=32000
    hgemm_kernel<0, 128><<<dim3(Vq / 128, Rq / 128), 128, smem128>>>(
        lnh, whd, (const float*)nullptr, logits, Rq, Vq, Dq);
}